// round 12
// baseline (speedup 1.0000x reference)
#include <cuda_runtime.h>
#include <math.h>

// Problem constants
#define NV 35709
#define NF 70789
#define NB 64
#define TN (3*NV)          // 107127
#define KC 224             // 80 id + 64 ex + 80 tex coeff columns

// ---------------- scratch (static __device__ — no allocations) ----------------
__device__ float d_cT[KC*NB];            // transposed coeffs: cT[k*64 + b]
__device__ float d_rotM[NB*9];           // per-batch rotation M (out = M @ v)
__device__ float d_gg[NB*27];            // SH gains: gg[b*27 + k*3 + c]
__device__ float d_shape[(size_t)NB*TN]; // pre-rotation shape, batch-major
__device__ float d_tex[(size_t)NB*TN];   // texture /255, batch-major
__device__ float d_fn[(size_t)NB*(NF+1)*3]; // face normals (+zero row at NF)

// ---------------- kernel 0: coeff transpose, rotation matrices, SH gains ------
__global__ void setup_k(const float* __restrict__ coeffs,
                        const float* __restrict__ init_lit)
{
    int tid = threadIdx.x;
    for (int idx = tid; idx < KC*NB; idx += blockDim.x) {
        int k = idx >> 6, b = idx & 63;
        d_cT[idx] = coeffs[b*257 + k];
    }
    for (int idx = tid; idx < NB*27; idx += blockDim.x) {
        int b = idx / 27, r = idx % 27;
        int k = r / 3, c = r % 3;
        d_gg[idx] = coeffs[b*257 + 227 + c*9 + k] + init_lit[k];
    }
    if (tid < NB) {
        int b = tid;
        float ax = coeffs[b*257+224], ay = coeffs[b*257+225], az = coeffs[b*257+226];
        float cx = cosf(ax), sx = sinf(ax);
        float cy = cosf(ay), sy = sinf(ay);
        float cz = cosf(az), sz = sinf(az);
        float* M = d_rotM + b*9;
        // M = Rz * Ry * Rx; v_row @ rot == M @ v
        M[0] = cz*cy;  M[1] = cz*sy*sx - sz*cx;  M[2] = cz*sy*cx + sz*sx;
        M[3] = sz*cy;  M[4] = sz*sy*sx + cz*cx;  M[5] = sz*sy*cx - cz*sx;
        M[6] = -sy;    M[7] = cy*sx;             M[8] = cy*cx;
    }
}

// ---------------- kernel 1: fused shape + texture GEMM ------------------------
// Mirrors the reference's fp op order exactly:
//   shape = (idGemm + exGemm) + meanshape   (three separately rounded stages,
//   each GEMM an ascending-k FFMA chain from acc=0 — matching cuBLAS/Triton)
// Block: 256 threads, tile = 128 rows x 64 batches; thread: 4 rows x 8 batches.
__global__ __launch_bounds__(256) void gemm_k(
    const float* __restrict__ idBase, const float* __restrict__ exBase,
    const float* __restrict__ texBase, const float* __restrict__ meanshape,
    const float* __restrict__ meantex)
{
    __shared__ float T[128*65];   // transpose staging (pad 65 -> conflict-free)
    const int tid = threadIdx.x;
    const int tr = tid >> 3, tb = tid & 7;
    const int rowBase = blockIdx.x << 7;
    const int r0 = rowBase + tr*4;

    float acc1[4][8], acc2[4][8];
    #pragma unroll
    for (int rr = 0; rr < 4; rr++)
        #pragma unroll
        for (int bb = 0; bb < 8; bb++) { acc1[rr][bb] = 0.f; acc2[rr][bb] = 0.f; }

    // --- id base: K = 80, coeff rows [0,80)  -> acc1
    for (int k = 0; k < 80; k += 4) {
        float4 bv[4];
        #pragma unroll
        for (int rr = 0; rr < 4; rr++) {
            int row = r0 + rr;
            bv[rr] = (row < TN) ? *(const float4*)(idBase + (size_t)row*80 + k)
                                : make_float4(0.f,0.f,0.f,0.f);
        }
        #pragma unroll
        for (int q = 0; q < 4; q++) {
            float4 c0 = *(const float4*)(d_cT + (k+q)*64 + tb*8);
            float4 c1 = *(const float4*)(d_cT + (k+q)*64 + tb*8 + 4);
            float cb[8] = {c0.x,c0.y,c0.z,c0.w,c1.x,c1.y,c1.z,c1.w};
            #pragma unroll
            for (int rr = 0; rr < 4; rr++) {
                float bq = ((const float*)&bv[rr])[q];
                #pragma unroll
                for (int bb = 0; bb < 8; bb++)
                    acc1[rr][bb] = fmaf(bq, cb[bb], acc1[rr][bb]);
            }
        }
    }
    // --- ex base: K = 64, coeff rows [80,144) -> acc2 (separate rounding!)
    for (int k = 0; k < 64; k += 4) {
        float4 bv[4];
        #pragma unroll
        for (int rr = 0; rr < 4; rr++) {
            int row = r0 + rr;
            bv[rr] = (row < TN) ? *(const float4*)(exBase + (size_t)row*64 + k)
                                : make_float4(0.f,0.f,0.f,0.f);
        }
        #pragma unroll
        for (int q = 0; q < 4; q++) {
            float4 c0 = *(const float4*)(d_cT + (80+k+q)*64 + tb*8);
            float4 c1 = *(const float4*)(d_cT + (80+k+q)*64 + tb*8 + 4);
            float cb[8] = {c0.x,c0.y,c0.z,c0.w,c1.x,c1.y,c1.z,c1.w};
            #pragma unroll
            for (int rr = 0; rr < 4; rr++) {
                float bq = ((const float*)&bv[rr])[q];
                #pragma unroll
                for (int bb = 0; bb < 8; bb++)
                    acc2[rr][bb] = fmaf(bq, cb[bb], acc2[rr][bb]);
            }
        }
    }

    // shape = (id + ex) + ms, exact reference op order
    float ms[4];
    #pragma unroll
    for (int rr = 0; rr < 4; rr++)
        ms[rr] = (r0+rr < TN) ? meanshape[r0+rr] : 0.f;
    #pragma unroll
    for (int rr = 0; rr < 4; rr++)
        #pragma unroll
        for (int bb = 0; bb < 8; bb++)
            T[(tr*4+rr)*65 + tb*8+bb] =
                __fadd_rn(__fadd_rn(acc1[rr][bb], acc2[rr][bb]), ms[rr]);
    __syncthreads();
    for (int i = tid; i < 128*64; i += 256) {
        int b = i >> 7, r = i & 127;
        int row = rowBase + r;
        if (row < TN) d_shape[(size_t)b*TN + row] = T[r*65 + b];
    }
    __syncthreads();

    // --- tex base: K = 80, coeff rows [144,224) -> reuse acc1
    #pragma unroll
    for (int rr = 0; rr < 4; rr++)
        #pragma unroll
        for (int bb = 0; bb < 8; bb++) acc1[rr][bb] = 0.f;
    for (int k = 0; k < 80; k += 4) {
        float4 bv[4];
        #pragma unroll
        for (int rr = 0; rr < 4; rr++) {
            int row = r0 + rr;
            bv[rr] = (row < TN) ? *(const float4*)(texBase + (size_t)row*80 + k)
                                : make_float4(0.f,0.f,0.f,0.f);
        }
        #pragma unroll
        for (int q = 0; q < 4; q++) {
            float4 c0 = *(const float4*)(d_cT + (144+k+q)*64 + tb*8);
            float4 c1 = *(const float4*)(d_cT + (144+k+q)*64 + tb*8 + 4);
            float cb[8] = {c0.x,c0.y,c0.z,c0.w,c1.x,c1.y,c1.z,c1.w};
            #pragma unroll
            for (int rr = 0; rr < 4; rr++) {
                float bq = ((const float*)&bv[rr])[q];
                #pragma unroll
                for (int bb = 0; bb < 8; bb++)
                    acc1[rr][bb] = fmaf(bq, cb[bb], acc1[rr][bb]);
            }
        }
    }
    float mt[4];
    #pragma unroll
    for (int rr = 0; rr < 4; rr++)
        mt[rr] = (r0+rr < TN) ? meantex[r0+rr] : 0.f;
    #pragma unroll
    for (int rr = 0; rr < 4; rr++)
        #pragma unroll
        for (int bb = 0; bb < 8; bb++)
            T[(tr*4+rr)*65 + tb*8+bb] =
                __fdiv_rn(__fadd_rn(acc1[rr][bb], mt[rr]), 255.0f);
    __syncthreads();
    for (int i = tid; i < 128*64; i += 256) {
        int b = i >> 7, r = i & 127;
        int row = rowBase + r;
        if (row < TN) d_tex[(size_t)b*TN + row] = T[r*65 + b];
    }
}

// ---------------- kernel 2: rigid transform -> face_vertex --------------------
__global__ void transform_k(const float* __restrict__ coeffs,
                            float* __restrict__ out)
{
    int v = blockIdx.x * blockDim.x + threadIdx.x;
    int b = blockIdx.y;
    if (v >= NV) return;
    const float* M = d_rotM + b*9;
    const float* S = d_shape + (size_t)b*TN + 3*(size_t)v;
    float x = S[0], y = S[1], z = S[2];
    float tx = coeffs[b*257+254], ty = coeffs[b*257+255], tz = coeffs[b*257+256];
    float px = fmaf(M[0],x, fmaf(M[1],y, fmaf(M[2],z, tx)));
    float py = fmaf(M[3],x, fmaf(M[4],y, fmaf(M[5],z, ty)));
    float pz = fmaf(M[6],x, fmaf(M[7],y, fmaf(M[8],z, tz)));
    float* o = out + ((size_t)b*NV + v)*3;
    o[0] = px; o[1] = py; o[2] = 10.0f - pz;   // CAMERA_DISTANCE - z
}

// ---------------- kernel 3: per-face normals ----------------------------------
// Cross product replicates XLA/LLVM's FMA contraction of fsub(fmul,fmul):
//   nx = fma(ay, bz, -(az*by))
// For faces with v0==v2 (e2 == -e1 exactly) this leaves the rounding residual
// of the product — the SAME deterministic "garbage" unit normal the reference
// produces — provided d_shape matches the reference bitwise (hence the GEMM op
// ordering above). v0==v1 / v1==v2 cases are exactly zero under any scheme.
__global__ void fnorm_k(const int* __restrict__ face_buf)
{
    int f = blockIdx.x * blockDim.x + threadIdx.x;
    int b = blockIdx.y;
    if (f > NF) return;
    float* o = d_fn + ((size_t)b*(NF+1) + f)*3;
    if (f == NF) { o[0] = 0.f; o[1] = 0.f; o[2] = 0.f; return; }
    int v0 = face_buf[f*3+0], v1 = face_buf[f*3+1], v2 = face_buf[f*3+2];
    const float* S = d_shape + (size_t)b*TN;
    float p0x = S[3*v0], p0y = S[3*v0+1], p0z = S[3*v0+2];
    float p1x = S[3*v1], p1y = S[3*v1+1], p1z = S[3*v1+2];
    float p2x = S[3*v2], p2y = S[3*v2+1], p2z = S[3*v2+2];
    float ax = __fsub_rn(p0x, p1x), ay = __fsub_rn(p0y, p1y), az = __fsub_rn(p0z, p1z);
    float bx = __fsub_rn(p1x, p2x), by = __fsub_rn(p1y, p2y), bz = __fsub_rn(p1z, p2z);
    float nx = fmaf(ay, bz, -__fmul_rn(az, by));
    float ny = fmaf(az, bx, -__fmul_rn(ax, bz));
    float nz = fmaf(ax, by, -__fmul_rn(ay, bx));
    float nrm = sqrtf(nx*nx + ny*ny + nz*nz);
    float den = fmaxf(nrm, 1e-12f);
    o[0] = __fdiv_rn(nx, den);
    o[1] = __fdiv_rn(ny, den);
    o[2] = __fdiv_rn(nz, den);
}

// ---------------- kernel 4: vertex normals + SH color -------------------------
__global__ void color_k(const int* __restrict__ point_buf,
                        float* __restrict__ out)
{
    int v = blockIdx.x * blockDim.x + threadIdx.x;
    int b = blockIdx.y;
    if (v >= NV) return;
    const float* FN = d_fn + (size_t)b*(NF+1)*3;
    float sx = 0.f, sy = 0.f, sz = 0.f;
    #pragma unroll
    for (int k = 0; k < 8; k++) {
        int f = point_buf[v*8 + k];
        sx = __fadd_rn(sx, FN[3*f]);
        sy = __fadd_rn(sy, FN[3*f+1]);
        sz = __fadd_rn(sz, FN[3*f+2]);
    }
    float nrm = sqrtf(sx*sx + sy*sy + sz*sz);
    float den = fmaxf(nrm, 1e-12f);
    sx = __fdiv_rn(sx, den);
    sy = __fdiv_rn(sy, den);
    sz = __fdiv_rn(sz, den);
    const float* M = d_rotM + b*9;
    float nx = fmaf(M[0],sx, fmaf(M[1],sy, M[2]*sz));
    float ny = fmaf(M[3],sx, fmaf(M[4],sy, M[5]*sz));
    float nz = fmaf(M[6],sx, fmaf(M[7],sy, M[8]*sz));

    float Y[9];
    Y[0] = 0.886226925452758f;
    Y[1] = -1.772453850905516f * ny;
    Y[2] =  1.772453850905516f * nz;
    Y[3] = -1.772453850905516f * nx;
    Y[4] =  2.427050983124842f * nx * ny;
    Y[5] = -2.427050983124842f * ny * nz;
    Y[6] =  0.700629269224046f * (3.0f*nz*nz - 1.0f);
    Y[7] = -2.427050983124842f * nx * nz;
    Y[8] =  1.213525491562421f * (nx*nx - ny*ny);

    const float* g = d_gg + b*27;
    float cr = 0.f, cg = 0.f, cb = 0.f;
    #pragma unroll
    for (int k = 0; k < 9; k++) {
        cr = fmaf(Y[k], g[k*3+0], cr);
        cg = fmaf(Y[k], g[k*3+1], cg);
        cb = fmaf(Y[k], g[k*3+2], cb);
    }
    const float* Tx = d_tex + (size_t)b*TN + 3*(size_t)v;
    float* o = out + (size_t)NB*NV*3 + ((size_t)b*NV + v)*3;
    o[0] = cr * Tx[0];
    o[1] = cg * Tx[1];
    o[2] = cb * Tx[2];
}

// ---------------- kernel 5: landmarks -----------------------------------------
__global__ void lm_k(const int* __restrict__ keypoints,
                     const float* __restrict__ P,
                     const float* __restrict__ fv,
                     float* __restrict__ out)
{
    int j = threadIdx.x;
    int b = blockIdx.x;
    if (j >= 68) return;
    int v = keypoints[j];
    const float* p = fv + ((size_t)b*NV + v)*3;
    float x = p[0], y = p[1], z = p[2];
    float px = x*P[0] + y*P[3] + z*P[6];
    float py = x*P[1] + y*P[4] + z*P[7];
    float pz = x*P[2] + y*P[5] + z*P[8];
    float* o = out + (size_t)2*NB*NV*3 + ((size_t)b*68 + j)*2;
    o[0] = __fdiv_rn(px, pz);
    o[1] = __fdiv_rn(py, pz);
}

// ---------------- launch -------------------------------------------------------
extern "C" void kernel_launch(void* const* d_in, const int* in_sizes, int n_in,
                              void* d_out, int out_size)
{
    const float* coeffs    = (const float*)d_in[0];
    const float* meanshape = (const float*)d_in[1];
    const float* idBase    = (const float*)d_in[2];
    const float* exBase    = (const float*)d_in[3];
    const float* meantex   = (const float*)d_in[4];
    const float* texBase   = (const float*)d_in[5];
    const float* persc     = (const float*)d_in[6];
    const float* init_lit  = (const float*)d_in[7];
    const int*   point_buf = (const int*)d_in[8];
    const int*   face_buf  = (const int*)d_in[9];
    const int*   keypoints = (const int*)d_in[10];
    float* out = (float*)d_out;

    setup_k<<<1, 256>>>(coeffs, init_lit);
    gemm_k<<<(TN + 127)/128, 256>>>(idBase, exBase, texBase, meanshape, meantex);

    dim3 gV((NV + 255)/256, NB);
    transform_k<<<gV, 256>>>(coeffs, out);

    dim3 gF((NF + 1 + 255)/256, NB);
    fnorm_k<<<gF, 256>>>(face_buf);

    color_k<<<gV, 256>>>(point_buf, out);

    lm_k<<<NB, 128>>>(keypoints, persc, out, out);
}

// round 13
// speedup vs baseline: 1.0923x; 1.0923x over previous
#include <cuda_runtime.h>
#include <math.h>

// Problem constants
#define NV 35709
#define NF 70789
#define NB 64
#define TN (3*NV)          // 107127
#define KC 224             // 80 id + 64 ex + 80 tex coeff columns

typedef unsigned long long u64;

// packed f32x2 FMA: each 32-bit lane is an independent correctly-rounded FMA,
// so per-output accumulation order (ascending k) is bitwise-identical to FFMA.
#define FMA2(acc, a, b) asm("fma.rn.f32x2 %0, %1, %2, %0;" : "+l"(acc) : "l"(a), "l"(b))

__device__ __forceinline__ u64 pack2(float s) {
    u64 d; unsigned v = __float_as_uint(s);
    asm("mov.b64 %0, {%1, %1};" : "=l"(d) : "r"(v));
    return d;
}
__device__ __forceinline__ void unpack2(u64 p, float& lo, float& hi) {
    unsigned a, b;
    asm("mov.b64 {%0, %1}, %2;" : "=r"(a), "=r"(b) : "l"(p));
    lo = __uint_as_float(a); hi = __uint_as_float(b);
}

// ---------------- scratch (static __device__ — no allocations) ----------------
__device__ float d_cT[KC*NB];                  // transposed coeffs: cT[k*64 + b]
__device__ float d_rotM[NB*9];                 // per-batch rotation M (out = M @ v)
__device__ float d_gg[NB*27];                  // SH gains
__device__ float4 d_shape4[(size_t)NB*NV];     // pre-rotation shape, padded, batch-major
__device__ float d_tex[(size_t)NB*TN];         // texture /255, batch-major
__device__ float4 d_fn4[(size_t)NB*(NF+1)];    // face normals padded (+zero row at NF)
__device__ int4  d_face4[NF];                  // padded face indices

// ---------------- kernel 0: coeff transpose, rotation matrices, SH gains ------
__global__ void setup_k(const float* __restrict__ coeffs,
                        const float* __restrict__ init_lit)
{
    int tid = threadIdx.x;
    for (int idx = tid; idx < KC*NB; idx += blockDim.x) {
        int k = idx >> 6, b = idx & 63;
        d_cT[idx] = coeffs[b*257 + k];
    }
    for (int idx = tid; idx < NB*27; idx += blockDim.x) {
        int b = idx / 27, r = idx % 27;
        int k = r / 3, c = r % 3;
        d_gg[idx] = coeffs[b*257 + 227 + c*9 + k] + init_lit[k];
    }
    if (tid < NB) {
        int b = tid;
        float ax = coeffs[b*257+224], ay = coeffs[b*257+225], az = coeffs[b*257+226];
        float cx = cosf(ax), sx = sinf(ax);
        float cy = cosf(ay), sy = sinf(ay);
        float cz = cosf(az), sz = sinf(az);
        float* M = d_rotM + b*9;
        M[0] = cz*cy;  M[1] = cz*sy*sx - sz*cx;  M[2] = cz*sy*cx + sz*sx;
        M[3] = sz*cy;  M[4] = sz*sy*sx + cz*cx;  M[5] = sz*sy*cx - cz*sx;
        M[6] = -sy;    M[7] = cy*sx;             M[8] = cy*cx;
    }
}

// pad face_buf [F,3] -> int4
__global__ void prep_k(const int* __restrict__ face_buf)
{
    int f = blockIdx.x * blockDim.x + threadIdx.x;
    if (f >= NF) return;
    d_face4[f] = make_int4(face_buf[f*3], face_buf[f*3+1], face_buf[f*3+2], 0);
}

// ---------------- kernel 1: fused shape + texture GEMM ------------------------
// Reference fp op order: shape = (idGemm + exGemm) + meanshape, each GEMM an
// ascending-k FFMA chain from acc=0. f32x2 packs two BATCH lanes per op —
// per-lane rounding identical to scalar FFMA.
__global__ __launch_bounds__(256) void gemm_k(
    const float* __restrict__ idBase, const float* __restrict__ exBase,
    const float* __restrict__ texBase, const float* __restrict__ meanshape,
    const float* __restrict__ meantex)
{
    __shared__ float T[128*65];
    const int tid = threadIdx.x;
    const int tr = tid >> 3, tb = tid & 7;
    const int rowBase = blockIdx.x << 7;
    const int r0 = rowBase + tr*4;

    u64 acc1[4][4], acc2[4][4];
    #pragma unroll
    for (int rr = 0; rr < 4; rr++)
        #pragma unroll
        for (int p = 0; p < 4; p++) { acc1[rr][p] = 0ull; acc2[rr][p] = 0ull; }

    // --- id base: K = 80 -> acc1
    for (int k = 0; k < 80; k += 4) {
        float4 bv[4];
        #pragma unroll
        for (int rr = 0; rr < 4; rr++) {
            int row = r0 + rr;
            bv[rr] = (row < TN) ? *(const float4*)(idBase + (size_t)row*80 + k)
                                : make_float4(0.f,0.f,0.f,0.f);
        }
        #pragma unroll
        for (int q = 0; q < 4; q++) {
            ulonglong2 cA = *(const ulonglong2*)(d_cT + (k+q)*64 + tb*8);
            ulonglong2 cB = *(const ulonglong2*)(d_cT + (k+q)*64 + tb*8 + 4);
            #pragma unroll
            for (int rr = 0; rr < 4; rr++) {
                u64 a2 = pack2(((const float*)&bv[rr])[q]);
                FMA2(acc1[rr][0], a2, cA.x);
                FMA2(acc1[rr][1], a2, cA.y);
                FMA2(acc1[rr][2], a2, cB.x);
                FMA2(acc1[rr][3], a2, cB.y);
            }
        }
    }
    // --- ex base: K = 64 -> acc2 (separately rounded GEMM)
    for (int k = 0; k < 64; k += 4) {
        float4 bv[4];
        #pragma unroll
        for (int rr = 0; rr < 4; rr++) {
            int row = r0 + rr;
            bv[rr] = (row < TN) ? *(const float4*)(exBase + (size_t)row*64 + k)
                                : make_float4(0.f,0.f,0.f,0.f);
        }
        #pragma unroll
        for (int q = 0; q < 4; q++) {
            ulonglong2 cA = *(const ulonglong2*)(d_cT + (80+k+q)*64 + tb*8);
            ulonglong2 cB = *(const ulonglong2*)(d_cT + (80+k+q)*64 + tb*8 + 4);
            #pragma unroll
            for (int rr = 0; rr < 4; rr++) {
                u64 a2 = pack2(((const float*)&bv[rr])[q]);
                FMA2(acc2[rr][0], a2, cA.x);
                FMA2(acc2[rr][1], a2, cA.y);
                FMA2(acc2[rr][2], a2, cB.x);
                FMA2(acc2[rr][3], a2, cB.y);
            }
        }
    }

    // shape = (id + ex) + ms, exact reference op order
    float ms[4];
    #pragma unroll
    for (int rr = 0; rr < 4; rr++)
        ms[rr] = (r0+rr < TN) ? meanshape[r0+rr] : 0.f;
    #pragma unroll
    for (int rr = 0; rr < 4; rr++)
        #pragma unroll
        for (int p = 0; p < 4; p++) {
            float i0, i1, e0, e1;
            unpack2(acc1[rr][p], i0, i1);
            unpack2(acc2[rr][p], e0, e1);
            T[(tr*4+rr)*65 + tb*8 + 2*p]     = __fadd_rn(__fadd_rn(i0, e0), ms[rr]);
            T[(tr*4+rr)*65 + tb*8 + 2*p + 1] = __fadd_rn(__fadd_rn(i1, e1), ms[rr]);
        }
    __syncthreads();
    for (int i = tid; i < 128*64; i += 256) {
        int b = i >> 7, r = i & 127;
        int row = rowBase + r;
        if (row < TN) {
            int v = row / 3, c = row - 3*v;
            ((float*)d_shape4)[((size_t)b*NV + v)*4 + c] = T[r*65 + b];
        }
    }
    __syncthreads();

    // --- tex base: K = 80 -> reuse acc1
    #pragma unroll
    for (int rr = 0; rr < 4; rr++)
        #pragma unroll
        for (int p = 0; p < 4; p++) acc1[rr][p] = 0ull;
    for (int k = 0; k < 80; k += 4) {
        float4 bv[4];
        #pragma unroll
        for (int rr = 0; rr < 4; rr++) {
            int row = r0 + rr;
            bv[rr] = (row < TN) ? *(const float4*)(texBase + (size_t)row*80 + k)
                                : make_float4(0.f,0.f,0.f,0.f);
        }
        #pragma unroll
        for (int q = 0; q < 4; q++) {
            ulonglong2 cA = *(const ulonglong2*)(d_cT + (144+k+q)*64 + tb*8);
            ulonglong2 cB = *(const ulonglong2*)(d_cT + (144+k+q)*64 + tb*8 + 4);
            #pragma unroll
            for (int rr = 0; rr < 4; rr++) {
                u64 a2 = pack2(((const float*)&bv[rr])[q]);
                FMA2(acc1[rr][0], a2, cA.x);
                FMA2(acc1[rr][1], a2, cA.y);
                FMA2(acc1[rr][2], a2, cB.x);
                FMA2(acc1[rr][3], a2, cB.y);
            }
        }
    }
    float mt[4];
    #pragma unroll
    for (int rr = 0; rr < 4; rr++)
        mt[rr] = (r0+rr < TN) ? meantex[r0+rr] : 0.f;
    #pragma unroll
    for (int rr = 0; rr < 4; rr++)
        #pragma unroll
        for (int p = 0; p < 4; p++) {
            float t0, t1;
            unpack2(acc1[rr][p], t0, t1);
            T[(tr*4+rr)*65 + tb*8 + 2*p]     = __fdiv_rn(__fadd_rn(t0, mt[rr]), 255.0f);
            T[(tr*4+rr)*65 + tb*8 + 2*p + 1] = __fdiv_rn(__fadd_rn(t1, mt[rr]), 255.0f);
        }
    __syncthreads();
    for (int i = tid; i < 128*64; i += 256) {
        int b = i >> 7, r = i & 127;
        int row = rowBase + r;
        if (row < TN) d_tex[(size_t)b*TN + row] = T[r*65 + b];
    }
}

// ---------------- kernel 2: rigid transform -> face_vertex --------------------
__global__ void transform_k(const float* __restrict__ coeffs,
                            float* __restrict__ out)
{
    int v = blockIdx.x * blockDim.x + threadIdx.x;
    int b = blockIdx.y;
    if (v >= NV) return;
    const float* M = d_rotM + b*9;
    float4 S = d_shape4[(size_t)b*NV + v];
    float x = S.x, y = S.y, z = S.z;
    float tx = coeffs[b*257+254], ty = coeffs[b*257+255], tz = coeffs[b*257+256];
    float px = fmaf(M[0],x, fmaf(M[1],y, fmaf(M[2],z, tx)));
    float py = fmaf(M[3],x, fmaf(M[4],y, fmaf(M[5],z, ty)));
    float pz = fmaf(M[6],x, fmaf(M[7],y, fmaf(M[8],z, tz)));
    float* o = out + ((size_t)b*NV + v)*3;
    o[0] = px; o[1] = py; o[2] = 10.0f - pz;
}

// ---------------- kernel 3: per-face normals ----------------------------------
// Cross product replicates XLA/LLVM's FMA contraction: fma(ay,bz, -(az*by)).
// Gathers are single aligned LDG.128 via float4-padded shape.
__global__ void fnorm_k()
{
    int f = blockIdx.x * blockDim.x + threadIdx.x;
    int b = blockIdx.y;
    if (f > NF) return;
    float4* o = d_fn4 + (size_t)b*(NF+1) + f;
    if (f == NF) { *o = make_float4(0.f,0.f,0.f,0.f); return; }
    int4 vi = d_face4[f];
    const float4* S = d_shape4 + (size_t)b*NV;
    float4 p0 = S[vi.x], p1 = S[vi.y], p2 = S[vi.z];
    float ax = __fsub_rn(p0.x, p1.x), ay = __fsub_rn(p0.y, p1.y), az = __fsub_rn(p0.z, p1.z);
    float bx = __fsub_rn(p1.x, p2.x), by = __fsub_rn(p1.y, p2.y), bz = __fsub_rn(p1.z, p2.z);
    float nx = fmaf(ay, bz, -__fmul_rn(az, by));
    float ny = fmaf(az, bx, -__fmul_rn(ax, bz));
    float nz = fmaf(ax, by, -__fmul_rn(ay, bx));
    float nrm = sqrtf(nx*nx + ny*ny + nz*nz);
    float den = fmaxf(nrm, 1e-12f);
    *o = make_float4(__fdiv_rn(nx, den), __fdiv_rn(ny, den), __fdiv_rn(nz, den), 0.f);
}

// ---------------- kernel 4: vertex normals + SH color -------------------------
__global__ void color_k(const int* __restrict__ point_buf,
                        float* __restrict__ out)
{
    int v = blockIdx.x * blockDim.x + threadIdx.x;
    int b = blockIdx.y;
    if (v >= NV) return;
    const float4* FN = d_fn4 + (size_t)b*(NF+1);
    int4 f0 = *(const int4*)(point_buf + v*8);
    int4 f1 = *(const int4*)(point_buf + v*8 + 4);
    int fi[8] = {f0.x,f0.y,f0.z,f0.w,f1.x,f1.y,f1.z,f1.w};
    float sx = 0.f, sy = 0.f, sz = 0.f;
    #pragma unroll
    for (int k = 0; k < 8; k++) {
        float4 n = FN[fi[k]];
        sx = __fadd_rn(sx, n.x);
        sy = __fadd_rn(sy, n.y);
        sz = __fadd_rn(sz, n.z);
    }
    float nrm = sqrtf(sx*sx + sy*sy + sz*sz);
    float den = fmaxf(nrm, 1e-12f);
    sx = __fdiv_rn(sx, den);
    sy = __fdiv_rn(sy, den);
    sz = __fdiv_rn(sz, den);
    const float* M = d_rotM + b*9;
    float nx = fmaf(M[0],sx, fmaf(M[1],sy, M[2]*sz));
    float ny = fmaf(M[3],sx, fmaf(M[4],sy, M[5]*sz));
    float nz = fmaf(M[6],sx, fmaf(M[7],sy, M[8]*sz));

    float Y[9];
    Y[0] = 0.886226925452758f;
    Y[1] = -1.772453850905516f * ny;
    Y[2] =  1.772453850905516f * nz;
    Y[3] = -1.772453850905516f * nx;
    Y[4] =  2.427050983124842f * nx * ny;
    Y[5] = -2.427050983124842f * ny * nz;
    Y[6] =  0.700629269224046f * (3.0f*nz*nz - 1.0f);
    Y[7] = -2.427050983124842f * nx * nz;
    Y[8] =  1.213525491562421f * (nx*nx - ny*ny);

    const float* g = d_gg + b*27;
    float cr = 0.f, cg = 0.f, cb = 0.f;
    #pragma unroll
    for (int k = 0; k < 9; k++) {
        cr = fmaf(Y[k], g[k*3+0], cr);
        cg = fmaf(Y[k], g[k*3+1], cg);
        cb = fmaf(Y[k], g[k*3+2], cb);
    }
    const float* Tx = d_tex + (size_t)b*TN + 3*(size_t)v;
    float* o = out + (size_t)NB*NV*3 + ((size_t)b*NV + v)*3;
    o[0] = cr * Tx[0];
    o[1] = cg * Tx[1];
    o[2] = cb * Tx[2];
}

// ---------------- kernel 5: landmarks -----------------------------------------
__global__ void lm_k(const int* __restrict__ keypoints,
                     const float* __restrict__ P,
                     const float* __restrict__ fv,
                     float* __restrict__ out)
{
    int j = threadIdx.x;
    int b = blockIdx.x;
    if (j >= 68) return;
    int v = keypoints[j];
    const float* p = fv + ((size_t)b*NV + v)*3;
    float x = p[0], y = p[1], z = p[2];
    float px = x*P[0] + y*P[3] + z*P[6];
    float py = x*P[1] + y*P[4] + z*P[7];
    float pz = x*P[2] + y*P[5] + z*P[8];
    float* o = out + (size_t)2*NB*NV*3 + ((size_t)b*68 + j)*2;
    o[0] = __fdiv_rn(px, pz);
    o[1] = __fdiv_rn(py, pz);
}

// ---------------- launch -------------------------------------------------------
extern "C" void kernel_launch(void* const* d_in, const int* in_sizes, int n_in,
                              void* d_out, int out_size)
{
    const float* coeffs    = (const float*)d_in[0];
    const float* meanshape = (const float*)d_in[1];
    const float* idBase    = (const float*)d_in[2];
    const float* exBase    = (const float*)d_in[3];
    const float* meantex   = (const float*)d_in[4];
    const float* texBase   = (const float*)d_in[5];
    const float* persc     = (const float*)d_in[6];
    const float* init_lit  = (const float*)d_in[7];
    const int*   point_buf = (const int*)d_in[8];
    const int*   face_buf  = (const int*)d_in[9];
    const int*   keypoints = (const int*)d_in[10];
    float* out = (float*)d_out;

    setup_k<<<1, 256>>>(coeffs, init_lit);
    prep_k<<<(NF + 255)/256, 256>>>(face_buf);
    gemm_k<<<(TN + 127)/128, 256>>>(idBase, exBase, texBase, meanshape, meantex);

    dim3 gV((NV + 255)/256, NB);
    transform_k<<<gV, 256>>>(coeffs, out);

    dim3 gF((NF + 1 + 255)/256, NB);
    fnorm_k<<<gF, 256>>>();

    color_k<<<gV, 256>>>(point_buf, out);

    lm_k<<<NB, 128>>>(keypoints, persc, out, out);
}

// round 14
// speedup vs baseline: 1.1250x; 1.0300x over previous
#include <cuda_runtime.h>
#include <math.h>

// Problem constants
#define NV 35709
#define NF 70789
#define NB 64
#define TN (3*NV)          // 107127
#define KC 224             // 80 id + 64 ex + 80 tex coeff columns

typedef unsigned long long u64;

// packed f32x2 FMA: each 32-bit lane is an independent correctly-rounded FMA,
// so per-output accumulation order (ascending k) is bitwise-identical to FFMA.
#define FMA2(acc, a, b) asm("fma.rn.f32x2 %0, %1, %2, %0;" : "+l"(acc) : "l"(a), "l"(b))

__device__ __forceinline__ u64 pack2(float s) {
    u64 d; unsigned v = __float_as_uint(s);
    asm("mov.b64 %0, {%1, %1};" : "=l"(d) : "r"(v));
    return d;
}
__device__ __forceinline__ void unpack2(u64 p, float& lo, float& hi) {
    unsigned a, b;
    asm("mov.b64 {%0, %1}, %2;" : "=r"(a), "=r"(b) : "l"(p));
    lo = __uint_as_float(a); hi = __uint_as_float(b);
}

// ---------------- scratch (static __device__ — no allocations) ----------------
// Vertex-major SoA planes: index = v*64 + b. Gather indices are shared across
// batches, so batch-inner warps turn every gather into a coalesced 128B load.
__device__ float d_cT[KC*NB];                    // transposed coeffs
__device__ float d_rotM[NB*9];                   // per-batch rotation
__device__ float d_gg[NB*27];                    // SH gains
__device__ float d_Sx[(size_t)NV*NB];            // shape x plane
__device__ float d_Sy[(size_t)NV*NB];            // shape y plane
__device__ float d_Sz[(size_t)NV*NB];            // shape z plane
__device__ float d_txR[(size_t)NV*NB];           // texture planes (/255)
__device__ float d_txG[(size_t)NV*NB];
__device__ float d_txB[(size_t)NV*NB];
__device__ float d_fnx[(size_t)(NF+1)*NB];       // face-normal planes (+zero row)
__device__ float d_fny[(size_t)(NF+1)*NB];
__device__ float d_fnz[(size_t)(NF+1)*NB];
__device__ int4  d_face4[NF];                    // padded face indices

// ---------------- kernel 0: coeff transpose, rotation matrices, SH gains ------
__global__ void setup_k(const float* __restrict__ coeffs,
                        const float* __restrict__ init_lit)
{
    int tid = threadIdx.x;
    for (int idx = tid; idx < KC*NB; idx += blockDim.x) {
        int k = idx >> 6, b = idx & 63;
        d_cT[idx] = coeffs[b*257 + k];
    }
    for (int idx = tid; idx < NB*27; idx += blockDim.x) {
        int b = idx / 27, r = idx % 27;
        int k = r / 3, c = r % 3;
        d_gg[idx] = coeffs[b*257 + 227 + c*9 + k] + init_lit[k];
    }
    if (tid < NB) {
        int b = tid;
        float ax = coeffs[b*257+224], ay = coeffs[b*257+225], az = coeffs[b*257+226];
        float cx = cosf(ax), sx = sinf(ax);
        float cy = cosf(ay), sy = sinf(ay);
        float cz = cosf(az), sz = sinf(az);
        float* M = d_rotM + b*9;
        M[0] = cz*cy;  M[1] = cz*sy*sx - sz*cx;  M[2] = cz*sy*cx + sz*sx;
        M[3] = sz*cy;  M[4] = sz*sy*sx + cz*cx;  M[5] = sz*sy*cx - cz*sx;
        M[6] = -sy;    M[7] = cy*sx;             M[8] = cy*cx;
    }
}

// pad face_buf [F,3] -> int4
__global__ void prep_k(const int* __restrict__ face_buf)
{
    int f = blockIdx.x * blockDim.x + threadIdx.x;
    if (f >= NF) return;
    d_face4[f] = make_int4(face_buf[f*3], face_buf[f*3+1], face_buf[f*3+2], 0);
}

// ---------------- kernel 1: fused shape + texture GEMM ------------------------
// Reference fp op order: shape = (idGemm + exGemm) + meanshape, each GEMM an
// ascending-k FFMA chain from acc=0. f32x2 packs two BATCH lanes per op.
__global__ __launch_bounds__(256) void gemm_k(
    const float* __restrict__ idBase, const float* __restrict__ exBase,
    const float* __restrict__ texBase, const float* __restrict__ meanshape,
    const float* __restrict__ meantex)
{
    __shared__ float T[128*65];
    const int tid = threadIdx.x;
    const int tr = tid >> 3, tb = tid & 7;
    const int rowBase = blockIdx.x << 7;
    const int r0 = rowBase + tr*4;

    u64 acc1[4][4], acc2[4][4];
    #pragma unroll
    for (int rr = 0; rr < 4; rr++)
        #pragma unroll
        for (int p = 0; p < 4; p++) { acc1[rr][p] = 0ull; acc2[rr][p] = 0ull; }

    // --- id base: K = 80 -> acc1
    for (int k = 0; k < 80; k += 4) {
        float4 bv[4];
        #pragma unroll
        for (int rr = 0; rr < 4; rr++) {
            int row = r0 + rr;
            bv[rr] = (row < TN) ? *(const float4*)(idBase + (size_t)row*80 + k)
                                : make_float4(0.f,0.f,0.f,0.f);
        }
        #pragma unroll
        for (int q = 0; q < 4; q++) {
            ulonglong2 cA = *(const ulonglong2*)(d_cT + (k+q)*64 + tb*8);
            ulonglong2 cB = *(const ulonglong2*)(d_cT + (k+q)*64 + tb*8 + 4);
            #pragma unroll
            for (int rr = 0; rr < 4; rr++) {
                u64 a2 = pack2(((const float*)&bv[rr])[q]);
                FMA2(acc1[rr][0], a2, cA.x);
                FMA2(acc1[rr][1], a2, cA.y);
                FMA2(acc1[rr][2], a2, cB.x);
                FMA2(acc1[rr][3], a2, cB.y);
            }
        }
    }
    // --- ex base: K = 64 -> acc2 (separately rounded GEMM)
    for (int k = 0; k < 64; k += 4) {
        float4 bv[4];
        #pragma unroll
        for (int rr = 0; rr < 4; rr++) {
            int row = r0 + rr;
            bv[rr] = (row < TN) ? *(const float4*)(exBase + (size_t)row*64 + k)
                                : make_float4(0.f,0.f,0.f,0.f);
        }
        #pragma unroll
        for (int q = 0; q < 4; q++) {
            ulonglong2 cA = *(const ulonglong2*)(d_cT + (80+k+q)*64 + tb*8);
            ulonglong2 cB = *(const ulonglong2*)(d_cT + (80+k+q)*64 + tb*8 + 4);
            #pragma unroll
            for (int rr = 0; rr < 4; rr++) {
                u64 a2 = pack2(((const float*)&bv[rr])[q]);
                FMA2(acc2[rr][0], a2, cA.x);
                FMA2(acc2[rr][1], a2, cA.y);
                FMA2(acc2[rr][2], a2, cB.x);
                FMA2(acc2[rr][3], a2, cB.y);
            }
        }
    }

    // shape = (id + ex) + ms, exact reference op order
    float ms[4];
    #pragma unroll
    for (int rr = 0; rr < 4; rr++)
        ms[rr] = (r0+rr < TN) ? meanshape[r0+rr] : 0.f;
    #pragma unroll
    for (int rr = 0; rr < 4; rr++)
        #pragma unroll
        for (int p = 0; p < 4; p++) {
            float i0, i1, e0, e1;
            unpack2(acc1[rr][p], i0, i1);
            unpack2(acc2[rr][p], e0, e1);
            T[(tr*4+rr)*65 + tb*8 + 2*p]     = __fadd_rn(__fadd_rn(i0, e0), ms[rr]);
            T[(tr*4+rr)*65 + tb*8 + 2*p + 1] = __fadd_rn(__fadd_rn(i1, e1), ms[rr]);
        }
    __syncthreads();
    // coalesced SoA store: batch-inner
    for (int i = tid; i < 128*64; i += 256) {
        int b = i & 63, r = i >> 6;
        int row = rowBase + r;
        if (row < TN) {
            int v = row / 3, c = row - 3*v;
            float* pl = (c == 0) ? d_Sx : (c == 1) ? d_Sy : d_Sz;
            pl[(size_t)v*64 + b] = T[r*65 + b];
        }
    }
    __syncthreads();

    // --- tex base: K = 80 -> reuse acc1
    #pragma unroll
    for (int rr = 0; rr < 4; rr++)
        #pragma unroll
        for (int p = 0; p < 4; p++) acc1[rr][p] = 0ull;
    for (int k = 0; k < 80; k += 4) {
        float4 bv[4];
        #pragma unroll
        for (int rr = 0; rr < 4; rr++) {
            int row = r0 + rr;
            bv[rr] = (row < TN) ? *(const float4*)(texBase + (size_t)row*80 + k)
                                : make_float4(0.f,0.f,0.f,0.f);
        }
        #pragma unroll
        for (int q = 0; q < 4; q++) {
            ulonglong2 cA = *(const ulonglong2*)(d_cT + (144+k+q)*64 + tb*8);
            ulonglong2 cB = *(const ulonglong2*)(d_cT + (144+k+q)*64 + tb*8 + 4);
            #pragma unroll
            for (int rr = 0; rr < 4; rr++) {
                u64 a2 = pack2(((const float*)&bv[rr])[q]);
                FMA2(acc1[rr][0], a2, cA.x);
                FMA2(acc1[rr][1], a2, cA.y);
                FMA2(acc1[rr][2], a2, cB.x);
                FMA2(acc1[rr][3], a2, cB.y);
            }
        }
    }
    float mt[4];
    #pragma unroll
    for (int rr = 0; rr < 4; rr++)
        mt[rr] = (r0+rr < TN) ? meantex[r0+rr] : 0.f;
    #pragma unroll
    for (int rr = 0; rr < 4; rr++)
        #pragma unroll
        for (int p = 0; p < 4; p++) {
            float t0, t1;
            unpack2(acc1[rr][p], t0, t1);
            T[(tr*4+rr)*65 + tb*8 + 2*p]     = __fdiv_rn(__fadd_rn(t0, mt[rr]), 255.0f);
            T[(tr*4+rr)*65 + tb*8 + 2*p + 1] = __fdiv_rn(__fadd_rn(t1, mt[rr]), 255.0f);
        }
    __syncthreads();
    for (int i = tid; i < 128*64; i += 256) {
        int b = i & 63, r = i >> 6;
        int row = rowBase + r;
        if (row < TN) {
            int v = row / 3, c = row - 3*v;
            float* pl = (c == 0) ? d_txR : (c == 1) ? d_txG : d_txB;
            pl[(size_t)v*64 + b] = T[r*65 + b];
        }
    }
}

// ---------------- kernel 2: rigid transform -> face_vertex --------------------
// batch-inner: warp = 32 consecutive b, same vertex. Reads coalesced; writes
// to the (b,v,3) output via smem transpose.
__global__ __launch_bounds__(256) void transform_k(const float* __restrict__ coeffs,
                                                   float* __restrict__ out)
{
    __shared__ float sm[12][65];
    int tid = threadIdx.x;
    int b = tid & 63, vl = tid >> 6;
    int v = blockIdx.x*4 + vl;
    if (v < NV) {
        const float* M = d_rotM + b*9;
        float x = d_Sx[(size_t)v*64 + b];
        float y = d_Sy[(size_t)v*64 + b];
        float z = d_Sz[(size_t)v*64 + b];
        float tx = coeffs[b*257+254], ty = coeffs[b*257+255], tz = coeffs[b*257+256];
        float px = fmaf(M[0],x, fmaf(M[1],y, fmaf(M[2],z, tx)));
        float py = fmaf(M[3],x, fmaf(M[4],y, fmaf(M[5],z, ty)));
        float pz = fmaf(M[6],x, fmaf(M[7],y, fmaf(M[8],z, tz)));
        sm[vl*3+0][b] = px;
        sm[vl*3+1][b] = py;
        sm[vl*3+2][b] = 10.0f - pz;
    }
    __syncthreads();
    int b2 = tid >> 2, q = tid & 3;
    size_t base = ((size_t)b2*NV + (size_t)blockIdx.x*4)*3;
    #pragma unroll
    for (int t = 0; t < 3; t++) {
        int e = q*3 + t;
        int vv = blockIdx.x*4 + (e/3);
        if (vv < NV) out[base + e] = sm[e][b2];
    }
}

// ---------------- kernel 3: per-face normals ----------------------------------
// Cross product replicates XLA/LLVM's FMA contraction: fma(ay,bz, -(az*by)).
// batch-inner: face indices are uniform broadcasts, shape reads coalesced.
__global__ __launch_bounds__(256) void fnorm_k()
{
    int tid = threadIdx.x;
    int b = tid & 63;
    int f = blockIdx.x*4 + (tid >> 6);
    if (f > NF) return;
    size_t o = (size_t)f*64 + b;
    if (f == NF) { d_fnx[o] = 0.f; d_fny[o] = 0.f; d_fnz[o] = 0.f; return; }
    int4 vi = d_face4[f];
    size_t i0 = (size_t)vi.x*64 + b, i1 = (size_t)vi.y*64 + b, i2 = (size_t)vi.z*64 + b;
    float p0x = d_Sx[i0], p0y = d_Sy[i0], p0z = d_Sz[i0];
    float p1x = d_Sx[i1], p1y = d_Sy[i1], p1z = d_Sz[i1];
    float p2x = d_Sx[i2], p2y = d_Sy[i2], p2z = d_Sz[i2];
    float ax = __fsub_rn(p0x, p1x), ay = __fsub_rn(p0y, p1y), az = __fsub_rn(p0z, p1z);
    float bx = __fsub_rn(p1x, p2x), by = __fsub_rn(p1y, p2y), bz = __fsub_rn(p1z, p2z);
    float nx = fmaf(ay, bz, -__fmul_rn(az, by));
    float ny = fmaf(az, bx, -__fmul_rn(ax, bz));
    float nz = fmaf(ax, by, -__fmul_rn(ay, bx));
    float nrm = sqrtf(nx*nx + ny*ny + nz*nz);
    float den = fmaxf(nrm, 1e-12f);
    d_fnx[o] = __fdiv_rn(nx, den);
    d_fny[o] = __fdiv_rn(ny, den);
    d_fnz[o] = __fdiv_rn(nz, den);
}

// ---------------- kernel 4: vertex normals + SH color -------------------------
__global__ __launch_bounds__(256) void color_k(const int* __restrict__ point_buf,
                                               float* __restrict__ out)
{
    __shared__ float sm[12][65];
    int tid = threadIdx.x;
    int b = tid & 63, vl = tid >> 6;
    int v = blockIdx.x*4 + vl;
    if (v < NV) {
        float sx = 0.f, sy = 0.f, sz = 0.f;
        #pragma unroll
        for (int k = 0; k < 8; k++) {
            int f = point_buf[v*8 + k];        // uniform broadcast across warp
            size_t idx = (size_t)f*64 + b;     // coalesced
            sx = __fadd_rn(sx, d_fnx[idx]);
            sy = __fadd_rn(sy, d_fny[idx]);
            sz = __fadd_rn(sz, d_fnz[idx]);
        }
        float nrm = sqrtf(sx*sx + sy*sy + sz*sz);
        float den = fmaxf(nrm, 1e-12f);
        sx = __fdiv_rn(sx, den);
        sy = __fdiv_rn(sy, den);
        sz = __fdiv_rn(sz, den);
        const float* M = d_rotM + b*9;
        float nx = fmaf(M[0],sx, fmaf(M[1],sy, M[2]*sz));
        float ny = fmaf(M[3],sx, fmaf(M[4],sy, M[5]*sz));
        float nz = fmaf(M[6],sx, fmaf(M[7],sy, M[8]*sz));

        float Y[9];
        Y[0] = 0.886226925452758f;
        Y[1] = -1.772453850905516f * ny;
        Y[2] =  1.772453850905516f * nz;
        Y[3] = -1.772453850905516f * nx;
        Y[4] =  2.427050983124842f * nx * ny;
        Y[5] = -2.427050983124842f * ny * nz;
        Y[6] =  0.700629269224046f * (3.0f*nz*nz - 1.0f);
        Y[7] = -2.427050983124842f * nx * nz;
        Y[8] =  1.213525491562421f * (nx*nx - ny*ny);

        const float* g = d_gg + b*27;
        float cr = 0.f, cg = 0.f, cb = 0.f;
        #pragma unroll
        for (int k = 0; k < 9; k++) {
            cr = fmaf(Y[k], g[k*3+0], cr);
            cg = fmaf(Y[k], g[k*3+1], cg);
            cb = fmaf(Y[k], g[k*3+2], cb);
        }
        size_t ti = (size_t)v*64 + b;
        sm[vl*3+0][b] = cr * d_txR[ti];
        sm[vl*3+1][b] = cg * d_txG[ti];
        sm[vl*3+2][b] = cb * d_txB[ti];
    }
    __syncthreads();
    int b2 = tid >> 2, q = tid & 3;
    size_t base = (size_t)NB*NV*3 + ((size_t)b2*NV + (size_t)blockIdx.x*4)*3;
    #pragma unroll
    for (int t = 0; t < 3; t++) {
        int e = q*3 + t;
        int vv = blockIdx.x*4 + (e/3);
        if (vv < NV) out[base + e] = sm[e][b2];
    }
}

// ---------------- kernel 5: landmarks -----------------------------------------
__global__ void lm_k(const int* __restrict__ keypoints,
                     const float* __restrict__ P,
                     const float* __restrict__ fv,
                     float* __restrict__ out)
{
    int j = threadIdx.x;
    int b = blockIdx.x;
    if (j >= 68) return;
    int v = keypoints[j];
    const float* p = fv + ((size_t)b*NV + v)*3;
    float x = p[0], y = p[1], z = p[2];
    float px = x*P[0] + y*P[3] + z*P[6];
    float py = x*P[1] + y*P[4] + z*P[7];
    float pz = x*P[2] + y*P[5] + z*P[8];
    float* o = out + (size_t)2*NB*NV*3 + ((size_t)b*68 + j)*2;
    o[0] = __fdiv_rn(px, pz);
    o[1] = __fdiv_rn(py, pz);
}

// ---------------- launch -------------------------------------------------------
extern "C" void kernel_launch(void* const* d_in, const int* in_sizes, int n_in,
                              void* d_out, int out_size)
{
    const float* coeffs    = (const float*)d_in[0];
    const float* meanshape = (const float*)d_in[1];
    const float* idBase    = (const float*)d_in[2];
    const float* exBase    = (const float*)d_in[3];
    const float* meantex   = (const float*)d_in[4];
    const float* texBase   = (const float*)d_in[5];
    const float* persc     = (const float*)d_in[6];
    const float* init_lit  = (const float*)d_in[7];
    const int*   point_buf = (const int*)d_in[8];
    const int*   face_buf  = (const int*)d_in[9];
    const int*   keypoints = (const int*)d_in[10];
    float* out = (float*)d_out;

    setup_k<<<1, 256>>>(coeffs, init_lit);
    prep_k<<<(NF + 255)/256, 256>>>(face_buf);
    gemm_k<<<(TN + 127)/128, 256>>>(idBase, exBase, texBase, meanshape, meantex);

    transform_k<<<(NV + 3)/4, 256>>>(coeffs, out);
    fnorm_k<<<(NF + 1 + 3)/4, 256>>>();
    color_k<<<(NV + 3)/4, 256>>>(point_buf, out);

    lm_k<<<NB, 128>>>(keypoints, persc, out, out);
}

// round 15
// speedup vs baseline: 1.1733x; 1.0429x over previous
#include <cuda_runtime.h>
#include <math.h>

// Problem constants
#define NV 35709
#define NF 70789
#define NB 64
#define TN (3*NV)          // 107127
#define KC 224             // 80 id + 64 ex + 80 tex coeff columns

typedef unsigned long long u64;

// packed f32x2 FMA: each 32-bit lane is an independent correctly-rounded FMA,
// so per-output accumulation order (ascending k) is bitwise-identical to FFMA.
#define FMA2(acc, a, b) asm("fma.rn.f32x2 %0, %1, %2, %0;" : "+l"(acc) : "l"(a), "l"(b))

__device__ __forceinline__ u64 pack2(float s) {
    u64 d; unsigned v = __float_as_uint(s);
    asm("mov.b64 %0, {%1, %1};" : "=l"(d) : "r"(v));
    return d;
}
__device__ __forceinline__ void unpack2(u64 p, float& lo, float& hi) {
    unsigned a, b;
    asm("mov.b64 {%0, %1}, %2;" : "=r"(a), "=r"(b) : "l"(p));
    lo = __uint_as_float(a); hi = __uint_as_float(b);
}

// ---------------- scratch (static __device__ — no allocations) ----------------
// Vertex-major SoA planes: index = v*64 + b. Gather indices are shared across
// batches, so batch-inner warps turn every gather into a coalesced 128B load.
__device__ float d_cT[KC*NB];                    // transposed coeffs
__device__ float d_rotM[NB*9];                   // per-batch rotation
__device__ float d_gg[NB*27];                    // SH gains
__device__ float d_Sx[(size_t)NV*NB];            // shape x plane
__device__ float d_Sy[(size_t)NV*NB];            // shape y plane
__device__ float d_Sz[(size_t)NV*NB];            // shape z plane
__device__ float d_txR[(size_t)NV*NB];           // texture planes (/255)
__device__ float d_txG[(size_t)NV*NB];
__device__ float d_txB[(size_t)NV*NB];
__device__ float d_fnx[(size_t)(NF+1)*NB];       // face-normal planes (+zero row)
__device__ float d_fny[(size_t)(NF+1)*NB];
__device__ float d_fnz[(size_t)(NF+1)*NB];
__device__ int4  d_face4[NF];                    // padded face indices

// ---------------- kernel 0: coeff transpose, rotation matrices, SH gains ------
__global__ void setup_k(const float* __restrict__ coeffs,
                        const float* __restrict__ init_lit)
{
    int tid = threadIdx.x;
    for (int idx = tid; idx < KC*NB; idx += blockDim.x) {
        int k = idx >> 6, b = idx & 63;
        d_cT[idx] = coeffs[b*257 + k];
    }
    for (int idx = tid; idx < NB*27; idx += blockDim.x) {
        int b = idx / 27, r = idx % 27;
        int k = r / 3, c = r % 3;
        d_gg[idx] = coeffs[b*257 + 227 + c*9 + k] + init_lit[k];
    }
    if (tid < NB) {
        int b = tid;
        float ax = coeffs[b*257+224], ay = coeffs[b*257+225], az = coeffs[b*257+226];
        float cx = cosf(ax), sx = sinf(ax);
        float cy = cosf(ay), sy = sinf(ay);
        float cz = cosf(az), sz = sinf(az);
        float* M = d_rotM + b*9;
        M[0] = cz*cy;  M[1] = cz*sy*sx - sz*cx;  M[2] = cz*sy*cx + sz*sx;
        M[3] = sz*cy;  M[4] = sz*sy*sx + cz*cx;  M[5] = sz*sy*cx - cz*sx;
        M[6] = -sy;    M[7] = cy*sx;             M[8] = cy*cx;
    }
}

// pad face_buf [F,3] -> int4
__global__ void prep_k(const int* __restrict__ face_buf)
{
    int f = blockIdx.x * blockDim.x + threadIdx.x;
    if (f >= NF) return;
    d_face4[f] = make_int4(face_buf[f*3], face_buf[f*3+1], face_buf[f*3+2], 0);
}

// ---------------- kernel 1: fused shape + texture GEMM ------------------------
// Reference fp op order: shape = (idGemm + exGemm) + meanshape, each GEMM an
// ascending-k FFMA chain from acc=0. f32x2 packs two BATCH lanes per op.
__global__ __launch_bounds__(256) void gemm_k(
    const float* __restrict__ idBase, const float* __restrict__ exBase,
    const float* __restrict__ texBase, const float* __restrict__ meanshape,
    const float* __restrict__ meantex)
{
    __shared__ float T[128*65];
    const int tid = threadIdx.x;
    const int tr = tid >> 3, tb = tid & 7;
    const int rowBase = blockIdx.x << 7;
    const int r0 = rowBase + tr*4;

    u64 acc1[4][4], acc2[4][4];
    #pragma unroll
    for (int rr = 0; rr < 4; rr++)
        #pragma unroll
        for (int p = 0; p < 4; p++) { acc1[rr][p] = 0ull; acc2[rr][p] = 0ull; }

    // --- id base: K = 80 -> acc1
    for (int k = 0; k < 80; k += 4) {
        float4 bv[4];
        #pragma unroll
        for (int rr = 0; rr < 4; rr++) {
            int row = r0 + rr;
            bv[rr] = (row < TN) ? *(const float4*)(idBase + (size_t)row*80 + k)
                                : make_float4(0.f,0.f,0.f,0.f);
        }
        #pragma unroll
        for (int q = 0; q < 4; q++) {
            ulonglong2 cA = *(const ulonglong2*)(d_cT + (k+q)*64 + tb*8);
            ulonglong2 cB = *(const ulonglong2*)(d_cT + (k+q)*64 + tb*8 + 4);
            #pragma unroll
            for (int rr = 0; rr < 4; rr++) {
                u64 a2 = pack2(((const float*)&bv[rr])[q]);
                FMA2(acc1[rr][0], a2, cA.x);
                FMA2(acc1[rr][1], a2, cA.y);
                FMA2(acc1[rr][2], a2, cB.x);
                FMA2(acc1[rr][3], a2, cB.y);
            }
        }
    }
    // --- ex base: K = 64 -> acc2 (separately rounded GEMM)
    for (int k = 0; k < 64; k += 4) {
        float4 bv[4];
        #pragma unroll
        for (int rr = 0; rr < 4; rr++) {
            int row = r0 + rr;
            bv[rr] = (row < TN) ? *(const float4*)(exBase + (size_t)row*64 + k)
                                : make_float4(0.f,0.f,0.f,0.f);
        }
        #pragma unroll
        for (int q = 0; q < 4; q++) {
            ulonglong2 cA = *(const ulonglong2*)(d_cT + (80+k+q)*64 + tb*8);
            ulonglong2 cB = *(const ulonglong2*)(d_cT + (80+k+q)*64 + tb*8 + 4);
            #pragma unroll
            for (int rr = 0; rr < 4; rr++) {
                u64 a2 = pack2(((const float*)&bv[rr])[q]);
                FMA2(acc2[rr][0], a2, cA.x);
                FMA2(acc2[rr][1], a2, cA.y);
                FMA2(acc2[rr][2], a2, cB.x);
                FMA2(acc2[rr][3], a2, cB.y);
            }
        }
    }

    // shape = (id + ex) + ms, exact reference op order
    float ms[4];
    #pragma unroll
    for (int rr = 0; rr < 4; rr++)
        ms[rr] = (r0+rr < TN) ? meanshape[r0+rr] : 0.f;
    #pragma unroll
    for (int rr = 0; rr < 4; rr++)
        #pragma unroll
        for (int p = 0; p < 4; p++) {
            float i0, i1, e0, e1;
            unpack2(acc1[rr][p], i0, i1);
            unpack2(acc2[rr][p], e0, e1);
            T[(tr*4+rr)*65 + tb*8 + 2*p]     = __fadd_rn(__fadd_rn(i0, e0), ms[rr]);
            T[(tr*4+rr)*65 + tb*8 + 2*p + 1] = __fadd_rn(__fadd_rn(i1, e1), ms[rr]);
        }
    __syncthreads();
    // coalesced SoA store: batch-inner, plane uniform per warp-row
    for (int i = tid; i < 128*64; i += 256) {
        int b = i & 63, r = i >> 6;
        int row = rowBase + r;
        if (row < TN) {
            int v = row / 3, c = row - 3*v;
            float* pl = (c == 0) ? d_Sx : (c == 1) ? d_Sy : d_Sz;
            pl[(size_t)v*64 + b] = T[r*65 + b];
        }
    }
    __syncthreads();

    // --- tex base: K = 80 -> reuse acc1
    #pragma unroll
    for (int rr = 0; rr < 4; rr++)
        #pragma unroll
        for (int p = 0; p < 4; p++) acc1[rr][p] = 0ull;
    for (int k = 0; k < 80; k += 4) {
        float4 bv[4];
        #pragma unroll
        for (int rr = 0; rr < 4; rr++) {
            int row = r0 + rr;
            bv[rr] = (row < TN) ? *(const float4*)(texBase + (size_t)row*80 + k)
                                : make_float4(0.f,0.f,0.f,0.f);
        }
        #pragma unroll
        for (int q = 0; q < 4; q++) {
            ulonglong2 cA = *(const ulonglong2*)(d_cT + (144+k+q)*64 + tb*8);
            ulonglong2 cB = *(const ulonglong2*)(d_cT + (144+k+q)*64 + tb*8 + 4);
            #pragma unroll
            for (int rr = 0; rr < 4; rr++) {
                u64 a2 = pack2(((const float*)&bv[rr])[q]);
                FMA2(acc1[rr][0], a2, cA.x);
                FMA2(acc1[rr][1], a2, cA.y);
                FMA2(acc1[rr][2], a2, cB.x);
                FMA2(acc1[rr][3], a2, cB.y);
            }
        }
    }
    float mt[4];
    #pragma unroll
    for (int rr = 0; rr < 4; rr++)
        mt[rr] = (r0+rr < TN) ? meantex[r0+rr] : 0.f;
    #pragma unroll
    for (int rr = 0; rr < 4; rr++)
        #pragma unroll
        for (int p = 0; p < 4; p++) {
            float t0, t1;
            unpack2(acc1[rr][p], t0, t1);
            T[(tr*4+rr)*65 + tb*8 + 2*p]     = __fdiv_rn(__fadd_rn(t0, mt[rr]), 255.0f);
            T[(tr*4+rr)*65 + tb*8 + 2*p + 1] = __fdiv_rn(__fadd_rn(t1, mt[rr]), 255.0f);
        }
    __syncthreads();
    for (int i = tid; i < 128*64; i += 256) {
        int b = i & 63, r = i >> 6;
        int row = rowBase + r;
        if (row < TN) {
            int v = row / 3, c = row - 3*v;
            float* pl = (c == 0) ? d_txR : (c == 1) ? d_txG : d_txB;
            pl[(size_t)v*64 + b] = T[r*65 + b];
        }
    }
}

// ---------------- kernel 2: rigid transform -> face_vertex --------------------
// 32 vertices x 64 batches per block. Phase 1: batch-inner coalesced reads +
// compute into smem. Phase 2: idx = b*96 + e mapping -> consecutive threads
// write consecutive global floats (fully coalesced); smem reads e*65+b are
// bank-conflict-free.
__global__ __launch_bounds__(256) void transform_k(const float* __restrict__ coeffs,
                                                   float* __restrict__ out)
{
    __shared__ float sm[96][65];
    const int tid = threadIdx.x;
    const int b = tid & 63;
    const int v0 = blockIdx.x * 32;
    const float* M = d_rotM + b*9;
    float m0=M[0],m1=M[1],m2=M[2],m3=M[3],m4=M[4],m5=M[5],m6=M[6],m7=M[7],m8=M[8];
    float tx = coeffs[b*257+254], ty = coeffs[b*257+255], tz = coeffs[b*257+256];
    #pragma unroll
    for (int it = 0; it < 8; it++) {
        int vl = (tid >> 6) + it*4;
        int v = v0 + vl;
        if (v < NV) {
            size_t si = (size_t)v*64 + b;
            float x = d_Sx[si], y = d_Sy[si], z = d_Sz[si];
            float px = fmaf(m0,x, fmaf(m1,y, fmaf(m2,z, tx)));
            float py = fmaf(m3,x, fmaf(m4,y, fmaf(m5,z, ty)));
            float pz = fmaf(m6,x, fmaf(m7,y, fmaf(m8,z, tz)));
            sm[vl*3+0][b] = px;
            sm[vl*3+1][b] = py;
            sm[vl*3+2][b] = 10.0f - pz;
        }
    }
    __syncthreads();
    int nv = NV - v0; if (nv > 32) nv = 32;
    if (nv == 32) {
        #pragma unroll
        for (int j = 0; j < 24; j++) {
            int idx = tid + j*256;           // 0..6143
            int bb = idx / 96, e = idx - bb*96;
            out[((size_t)bb*NV + v0)*3 + e] = sm[e][bb];
        }
    } else {
        int ne = 3*nv;
        for (int idx = tid; idx < 64*ne; idx += 256) {
            int bb = idx / ne, e = idx - bb*ne;
            out[((size_t)bb*NV + v0)*3 + e] = sm[e][bb];
        }
    }
}

// ---------------- kernel 3: per-face normals ----------------------------------
// Cross product replicates XLA/LLVM's FMA contraction: fma(ay,bz, -(az*by)).
// batch-inner: face indices are uniform broadcasts, shape reads coalesced.
__global__ __launch_bounds__(256) void fnorm_k()
{
    int tid = threadIdx.x;
    int b = tid & 63;
    int f = blockIdx.x*4 + (tid >> 6);
    if (f > NF) return;
    size_t o = (size_t)f*64 + b;
    if (f == NF) { d_fnx[o] = 0.f; d_fny[o] = 0.f; d_fnz[o] = 0.f; return; }
    int4 vi = d_face4[f];
    size_t i0 = (size_t)vi.x*64 + b, i1 = (size_t)vi.y*64 + b, i2 = (size_t)vi.z*64 + b;
    float p0x = d_Sx[i0], p0y = d_Sy[i0], p0z = d_Sz[i0];
    float p1x = d_Sx[i1], p1y = d_Sy[i1], p1z = d_Sz[i1];
    float p2x = d_Sx[i2], p2y = d_Sy[i2], p2z = d_Sz[i2];
    float ax = __fsub_rn(p0x, p1x), ay = __fsub_rn(p0y, p1y), az = __fsub_rn(p0z, p1z);
    float bx = __fsub_rn(p1x, p2x), by = __fsub_rn(p1y, p2y), bz = __fsub_rn(p1z, p2z);
    float nx = fmaf(ay, bz, -__fmul_rn(az, by));
    float ny = fmaf(az, bx, -__fmul_rn(ax, bz));
    float nz = fmaf(ax, by, -__fmul_rn(ay, bx));
    float nrm = sqrtf(nx*nx + ny*ny + nz*nz);
    float den = fmaxf(nrm, 1e-12f);
    d_fnx[o] = __fdiv_rn(nx, den);
    d_fny[o] = __fdiv_rn(ny, den);
    d_fnz[o] = __fdiv_rn(nz, den);
}

// ---------------- kernel 4: vertex normals + SH color -------------------------
// Same 32-vertex tile + coalesced write scheme as transform_k.
__global__ __launch_bounds__(256) void color_k(const int* __restrict__ point_buf,
                                               float* __restrict__ out)
{
    __shared__ float sm[96][65];
    const int tid = threadIdx.x;
    const int b = tid & 63;
    const int v0 = blockIdx.x * 32;
    const float* M = d_rotM + b*9;
    float m0=M[0],m1=M[1],m2=M[2],m3=M[3],m4=M[4],m5=M[5],m6=M[6],m7=M[7],m8=M[8];
    const float* g = d_gg + b*27;

    #pragma unroll
    for (int it = 0; it < 8; it++) {
        int vl = (tid >> 6) + it*4;
        int v = v0 + vl;
        if (v < NV) {
            float sx = 0.f, sy = 0.f, sz = 0.f;
            #pragma unroll
            for (int k = 0; k < 8; k++) {
                int f = point_buf[v*8 + k];        // uniform broadcast
                size_t idx = (size_t)f*64 + b;     // coalesced
                sx = __fadd_rn(sx, d_fnx[idx]);
                sy = __fadd_rn(sy, d_fny[idx]);
                sz = __fadd_rn(sz, d_fnz[idx]);
            }
            float nrm = sqrtf(sx*sx + sy*sy + sz*sz);
            float den = fmaxf(nrm, 1e-12f);
            sx = __fdiv_rn(sx, den);
            sy = __fdiv_rn(sy, den);
            sz = __fdiv_rn(sz, den);
            float nx = fmaf(m0,sx, fmaf(m1,sy, m2*sz));
            float ny = fmaf(m3,sx, fmaf(m4,sy, m5*sz));
            float nz = fmaf(m6,sx, fmaf(m7,sy, m8*sz));

            float Y[9];
            Y[0] = 0.886226925452758f;
            Y[1] = -1.772453850905516f * ny;
            Y[2] =  1.772453850905516f * nz;
            Y[3] = -1.772453850905516f * nx;
            Y[4] =  2.427050983124842f * nx * ny;
            Y[5] = -2.427050983124842f * ny * nz;
            Y[6] =  0.700629269224046f * (3.0f*nz*nz - 1.0f);
            Y[7] = -2.427050983124842f * nx * nz;
            Y[8] =  1.213525491562421f * (nx*nx - ny*ny);

            float cr = 0.f, cg = 0.f, cb = 0.f;
            #pragma unroll
            for (int k = 0; k < 9; k++) {
                cr = fmaf(Y[k], g[k*3+0], cr);
                cg = fmaf(Y[k], g[k*3+1], cg);
                cb = fmaf(Y[k], g[k*3+2], cb);
            }
            size_t ti = (size_t)v*64 + b;
            sm[vl*3+0][b] = cr * d_txR[ti];
            sm[vl*3+1][b] = cg * d_txG[ti];
            sm[vl*3+2][b] = cb * d_txB[ti];
        }
    }
    __syncthreads();
    int nv = NV - v0; if (nv > 32) nv = 32;
    size_t obase = (size_t)NB*NV*3;
    if (nv == 32) {
        #pragma unroll
        for (int j = 0; j < 24; j++) {
            int idx = tid + j*256;
            int bb = idx / 96, e = idx - bb*96;
            out[obase + ((size_t)bb*NV + v0)*3 + e] = sm[e][bb];
        }
    } else {
        int ne = 3*nv;
        for (int idx = tid; idx < 64*ne; idx += 256) {
            int bb = idx / ne, e = idx - bb*ne;
            out[obase + ((size_t)bb*NV + v0)*3 + e] = sm[e][bb];
        }
    }
}

// ---------------- kernel 5: landmarks -----------------------------------------
__global__ void lm_k(const int* __restrict__ keypoints,
                     const float* __restrict__ P,
                     const float* __restrict__ fv,
                     float* __restrict__ out)
{
    int j = threadIdx.x;
    int b = blockIdx.x;
    if (j >= 68) return;
    int v = keypoints[j];
    const float* p = fv + ((size_t)b*NV + v)*3;
    float x = p[0], y = p[1], z = p[2];
    float px = x*P[0] + y*P[3] + z*P[6];
    float py = x*P[1] + y*P[4] + z*P[7];
    float pz = x*P[2] + y*P[5] + z*P[8];
    float* o = out + (size_t)2*NB*NV*3 + ((size_t)b*68 + j)*2;
    o[0] = __fdiv_rn(px, pz);
    o[1] = __fdiv_rn(py, pz);
}

// ---------------- launch -------------------------------------------------------
extern "C" void kernel_launch(void* const* d_in, const int* in_sizes, int n_in,
                              void* d_out, int out_size)
{
    const float* coeffs    = (const float*)d_in[0];
    const float* meanshape = (const float*)d_in[1];
    const float* idBase    = (const float*)d_in[2];
    const float* exBase    = (const float*)d_in[3];
    const float* meantex   = (const float*)d_in[4];
    const float* texBase   = (const float*)d_in[5];
    const float* persc     = (const float*)d_in[6];
    const float* init_lit  = (const float*)d_in[7];
    const int*   point_buf = (const int*)d_in[8];
    const int*   face_buf  = (const int*)d_in[9];
    const int*   keypoints = (const int*)d_in[10];
    float* out = (float*)d_out;

    setup_k<<<1, 256>>>(coeffs, init_lit);
    prep_k<<<(NF + 255)/256, 256>>>(face_buf);
    gemm_k<<<(TN + 127)/128, 256>>>(idBase, exBase, texBase, meanshape, meantex);

    transform_k<<<(NV + 31)/32, 256>>>(coeffs, out);
    fnorm_k<<<(NF + 1 + 3)/4, 256>>>();
    color_k<<<(NV + 31)/32, 256>>>(point_buf, out);

    lm_k<<<NB, 128>>>(keypoints, persc, out, out);
}

// round 16
// speedup vs baseline: 1.3790x; 1.1753x over previous
#include <cuda_runtime.h>
#include <math.h>

// Problem constants
#define NV 35709
#define NF 70789
#define NB 64
#define TN (3*NV)          // 107127
#define KC 224             // 80 id + 64 ex + 80 tex coeff columns

typedef unsigned long long u64;

// packed f32x2 FMA: each 32-bit lane is an independent correctly-rounded FMA,
// so per-output accumulation order (ascending k) is bitwise-identical to FFMA.
#define FMA2(acc, a, b) asm("fma.rn.f32x2 %0, %1, %2, %0;" : "+l"(acc) : "l"(a), "l"(b))

__device__ __forceinline__ u64 pack2(float s) {
    u64 d; unsigned v = __float_as_uint(s);
    asm("mov.b64 %0, {%1, %1};" : "=l"(d) : "r"(v));
    return d;
}
__device__ __forceinline__ void unpack2(u64 p, float& lo, float& hi) {
    unsigned a, b;
    asm("mov.b64 {%0, %1}, %2;" : "=r"(a), "=r"(b) : "l"(p));
    lo = __uint_as_float(a); hi = __uint_as_float(b);
}

// ---------------- scratch (static __device__ — no allocations) ----------------
// Vertex-major SoA planes: index = v*64 + b. Gather indices are shared across
// batches, so batch-inner warps turn every gather into a coalesced 128B load.
__device__ float d_cT[KC*NB];                    // transposed coeffs
__device__ float d_rotM[NB*9];                   // per-batch rotation
__device__ float d_gg[NB*27];                    // SH gains
__device__ float d_Sx[(size_t)NV*NB];            // shape x plane
__device__ float d_Sy[(size_t)NV*NB];            // shape y plane
__device__ float d_Sz[(size_t)NV*NB];            // shape z plane
__device__ float d_txR[(size_t)NV*NB];           // texture planes (/255)
__device__ float d_txG[(size_t)NV*NB];
__device__ float d_txB[(size_t)NV*NB];
__device__ float d_fnx[(size_t)(NF+1)*NB];       // face-normal planes (+zero row)
__device__ float d_fny[(size_t)(NF+1)*NB];
__device__ float d_fnz[(size_t)(NF+1)*NB];
__device__ int4  d_face4[NF];                    // padded face indices

// ---------------- kernel 0: setup + face padding (merged) ---------------------
__global__ void setup_k(const float* __restrict__ coeffs,
                        const float* __restrict__ init_lit,
                        const int* __restrict__ face_buf)
{
    int gtid = blockIdx.x * blockDim.x + threadIdx.x;
    // pad face_buf [F,3] -> int4
    if (gtid < NF)
        d_face4[gtid] = make_int4(face_buf[gtid*3], face_buf[gtid*3+1], face_buf[gtid*3+2], 0);
    if (blockIdx.x == 0) {
        int tid = threadIdx.x;
        for (int idx = tid; idx < KC*NB; idx += blockDim.x) {
            int k = idx >> 6, b = idx & 63;
            d_cT[idx] = coeffs[b*257 + k];
        }
        for (int idx = tid; idx < NB*27; idx += blockDim.x) {
            int b = idx / 27, r = idx % 27;
            int k = r / 3, c = r % 3;
            d_gg[idx] = coeffs[b*257 + 227 + c*9 + k] + init_lit[k];
        }
        if (tid < NB) {
            int b = tid;
            float ax = coeffs[b*257+224], ay = coeffs[b*257+225], az = coeffs[b*257+226];
            float cx = cosf(ax), sx = sinf(ax);
            float cy = cosf(ay), sy = sinf(ay);
            float cz = cosf(az), sz = sinf(az);
            float* M = d_rotM + b*9;
            M[0] = cz*cy;  M[1] = cz*sy*sx - sz*cx;  M[2] = cz*sy*cx + sz*sx;
            M[3] = sz*cy;  M[4] = sz*sy*sx + cz*cx;  M[5] = sz*sy*cx - cz*sx;
            M[6] = -sy;    M[7] = cy*sx;             M[8] = cy*cx;
        }
    }
}

// ---------------- kernel 1: fused shape + texture GEMM ------------------------
// Reference fp op order: shape = (idGemm + exGemm) + meanshape, each GEMM an
// ascending-k FFMA chain from acc=0. f32x2 packs two BATCH lanes per op.
// A-tile loads are register double-buffered: chunk k+4's loads issue before
// chunk k's compute, hiding DRAM latency (the bases stream from HBM).
__global__ __launch_bounds__(256, 2) void gemm_k(
    const float* __restrict__ idBase, const float* __restrict__ exBase,
    const float* __restrict__ texBase, const float* __restrict__ meanshape,
    const float* __restrict__ meantex)
{
    __shared__ float T[128*65];
    const int tid = threadIdx.x;
    const int tr = tid >> 3, tb = tid & 7;
    const int rowBase = blockIdx.x << 7;
    const int r0 = rowBase + tr*4;
    const bool rowOK[4] = { r0 < TN, r0+1 < TN, r0+2 < TN, r0+3 < TN };

    u64 acc1[4][4], acc2[4][4];
    #pragma unroll
    for (int rr = 0; rr < 4; rr++)
        #pragma unroll
        for (int p = 0; p < 4; p++) { acc1[rr][p] = 0ull; acc2[rr][p] = 0ull; }

    float4 bv[4], bvn[4];

    // --- id base: K = 80 -> acc1
    #pragma unroll
    for (int rr = 0; rr < 4; rr++)
        bv[rr] = rowOK[rr] ? *(const float4*)(idBase + (size_t)(r0+rr)*80)
                           : make_float4(0.f,0.f,0.f,0.f);
    #pragma unroll 2
    for (int k = 0; k < 80; k += 4) {
        if (k + 4 < 80) {
            #pragma unroll
            for (int rr = 0; rr < 4; rr++)
                bvn[rr] = rowOK[rr] ? *(const float4*)(idBase + (size_t)(r0+rr)*80 + k + 4)
                                    : make_float4(0.f,0.f,0.f,0.f);
        }
        #pragma unroll
        for (int q = 0; q < 4; q++) {
            ulonglong2 cA = *(const ulonglong2*)(d_cT + (k+q)*64 + tb*8);
            ulonglong2 cB = *(const ulonglong2*)(d_cT + (k+q)*64 + tb*8 + 4);
            #pragma unroll
            for (int rr = 0; rr < 4; rr++) {
                u64 a2 = pack2(((const float*)&bv[rr])[q]);
                FMA2(acc1[rr][0], a2, cA.x);
                FMA2(acc1[rr][1], a2, cA.y);
                FMA2(acc1[rr][2], a2, cB.x);
                FMA2(acc1[rr][3], a2, cB.y);
            }
        }
        #pragma unroll
        for (int rr = 0; rr < 4; rr++) bv[rr] = bvn[rr];
    }

    // --- ex base: K = 64 -> acc2 (separately rounded GEMM)
    #pragma unroll
    for (int rr = 0; rr < 4; rr++)
        bv[rr] = rowOK[rr] ? *(const float4*)(exBase + (size_t)(r0+rr)*64)
                           : make_float4(0.f,0.f,0.f,0.f);
    #pragma unroll 2
    for (int k = 0; k < 64; k += 4) {
        if (k + 4 < 64) {
            #pragma unroll
            for (int rr = 0; rr < 4; rr++)
                bvn[rr] = rowOK[rr] ? *(const float4*)(exBase + (size_t)(r0+rr)*64 + k + 4)
                                    : make_float4(0.f,0.f,0.f,0.f);
        }
        #pragma unroll
        for (int q = 0; q < 4; q++) {
            ulonglong2 cA = *(const ulonglong2*)(d_cT + (80+k+q)*64 + tb*8);
            ulonglong2 cB = *(const ulonglong2*)(d_cT + (80+k+q)*64 + tb*8 + 4);
            #pragma unroll
            for (int rr = 0; rr < 4; rr++) {
                u64 a2 = pack2(((const float*)&bv[rr])[q]);
                FMA2(acc2[rr][0], a2, cA.x);
                FMA2(acc2[rr][1], a2, cA.y);
                FMA2(acc2[rr][2], a2, cB.x);
                FMA2(acc2[rr][3], a2, cB.y);
            }
        }
        #pragma unroll
        for (int rr = 0; rr < 4; rr++) bv[rr] = bvn[rr];
    }

    // shape = (id + ex) + ms, exact reference op order
    float ms[4];
    #pragma unroll
    for (int rr = 0; rr < 4; rr++)
        ms[rr] = rowOK[rr] ? meanshape[r0+rr] : 0.f;
    #pragma unroll
    for (int rr = 0; rr < 4; rr++)
        #pragma unroll
        for (int p = 0; p < 4; p++) {
            float i0, i1, e0, e1;
            unpack2(acc1[rr][p], i0, i1);
            unpack2(acc2[rr][p], e0, e1);
            T[(tr*4+rr)*65 + tb*8 + 2*p]     = __fadd_rn(__fadd_rn(i0, e0), ms[rr]);
            T[(tr*4+rr)*65 + tb*8 + 2*p + 1] = __fadd_rn(__fadd_rn(i1, e1), ms[rr]);
        }
    __syncthreads();
    // coalesced SoA store: batch-inner
    for (int i = tid; i < 128*64; i += 256) {
        int b = i & 63, r = i >> 6;
        int row = rowBase + r;
        if (row < TN) {
            int v = row / 3, c = row - 3*v;
            float* pl = (c == 0) ? d_Sx : (c == 1) ? d_Sy : d_Sz;
            pl[(size_t)v*64 + b] = T[r*65 + b];
        }
    }
    __syncthreads();

    // --- tex base: K = 80 -> reuse acc1
    #pragma unroll
    for (int rr = 0; rr < 4; rr++)
        #pragma unroll
        for (int p = 0; p < 4; p++) acc1[rr][p] = 0ull;
    #pragma unroll
    for (int rr = 0; rr < 4; rr++)
        bv[rr] = rowOK[rr] ? *(const float4*)(texBase + (size_t)(r0+rr)*80)
                           : make_float4(0.f,0.f,0.f,0.f);
    #pragma unroll 2
    for (int k = 0; k < 80; k += 4) {
        if (k + 4 < 80) {
            #pragma unroll
            for (int rr = 0; rr < 4; rr++)
                bvn[rr] = rowOK[rr] ? *(const float4*)(texBase + (size_t)(r0+rr)*80 + k + 4)
                                    : make_float4(0.f,0.f,0.f,0.f);
        }
        #pragma unroll
        for (int q = 0; q < 4; q++) {
            ulonglong2 cA = *(const ulonglong2*)(d_cT + (144+k+q)*64 + tb*8);
            ulonglong2 cB = *(const ulonglong2*)(d_cT + (144+k+q)*64 + tb*8 + 4);
            #pragma unroll
            for (int rr = 0; rr < 4; rr++) {
                u64 a2 = pack2(((const float*)&bv[rr])[q]);
                FMA2(acc1[rr][0], a2, cA.x);
                FMA2(acc1[rr][1], a2, cA.y);
                FMA2(acc1[rr][2], a2, cB.x);
                FMA2(acc1[rr][3], a2, cB.y);
            }
        }
        #pragma unroll
        for (int rr = 0; rr < 4; rr++) bv[rr] = bvn[rr];
    }
    float mt[4];
    #pragma unroll
    for (int rr = 0; rr < 4; rr++)
        mt[rr] = rowOK[rr] ? meantex[r0+rr] : 0.f;
    #pragma unroll
    for (int rr = 0; rr < 4; rr++)
        #pragma unroll
        for (int p = 0; p < 4; p++) {
            float t0, t1;
            unpack2(acc1[rr][p], t0, t1);
            T[(tr*4+rr)*65 + tb*8 + 2*p]     = __fdiv_rn(__fadd_rn(t0, mt[rr]), 255.0f);
            T[(tr*4+rr)*65 + tb*8 + 2*p + 1] = __fdiv_rn(__fadd_rn(t1, mt[rr]), 255.0f);
        }
    __syncthreads();
    for (int i = tid; i < 128*64; i += 256) {
        int b = i & 63, r = i >> 6;
        int row = rowBase + r;
        if (row < TN) {
            int v = row / 3, c = row - 3*v;
            float* pl = (c == 0) ? d_txR : (c == 1) ? d_txG : d_txB;
            pl[(size_t)v*64 + b] = T[r*65 + b];
        }
    }
}

// ---------------- kernel 2: rigid transform -> face_vertex --------------------
// 32 vertices x 64 batches per block; coalesced phase-2 writes.
__global__ __launch_bounds__(256) void transform_k(const float* __restrict__ coeffs,
                                                   float* __restrict__ out)
{
    __shared__ float sm[96][65];
    const int tid = threadIdx.x;
    const int b = tid & 63;
    const int v0 = blockIdx.x * 32;
    const float* M = d_rotM + b*9;
    float m0=M[0],m1=M[1],m2=M[2],m3=M[3],m4=M[4],m5=M[5],m6=M[6],m7=M[7],m8=M[8];
    float tx = coeffs[b*257+254], ty = coeffs[b*257+255], tz = coeffs[b*257+256];
    #pragma unroll
    for (int it = 0; it < 8; it++) {
        int vl = (tid >> 6) + it*4;
        int v = v0 + vl;
        if (v < NV) {
            size_t si = (size_t)v*64 + b;
            float x = d_Sx[si], y = d_Sy[si], z = d_Sz[si];
            float px = fmaf(m0,x, fmaf(m1,y, fmaf(m2,z, tx)));
            float py = fmaf(m3,x, fmaf(m4,y, fmaf(m5,z, ty)));
            float pz = fmaf(m6,x, fmaf(m7,y, fmaf(m8,z, tz)));
            sm[vl*3+0][b] = px;
            sm[vl*3+1][b] = py;
            sm[vl*3+2][b] = 10.0f - pz;
        }
    }
    __syncthreads();
    int nv = NV - v0; if (nv > 32) nv = 32;
    if (nv == 32) {
        #pragma unroll
        for (int j = 0; j < 24; j++) {
            int idx = tid + j*256;           // 0..6143
            int bb = (unsigned)idx / 96u, e = idx - bb*96;
            out[((size_t)bb*NV + v0)*3 + e] = sm[e][bb];
        }
    } else {
        int ne = 3*nv;
        for (int idx = tid; idx < 64*ne; idx += 256) {
            int bb = idx / ne, e = idx - bb*ne;
            out[((size_t)bb*NV + v0)*3 + e] = sm[e][bb];
        }
    }
}

// ---------------- kernel 3: per-face normals ----------------------------------
// Cross product replicates XLA/LLVM's FMA contraction: fma(ay,bz, -(az*by)).
__global__ __launch_bounds__(256) void fnorm_k()
{
    int tid = threadIdx.x;
    int b = tid & 63;
    int f = blockIdx.x*4 + (tid >> 6);
    if (f > NF) return;
    size_t o = (size_t)f*64 + b;
    if (f == NF) { d_fnx[o] = 0.f; d_fny[o] = 0.f; d_fnz[o] = 0.f; return; }
    int4 vi = d_face4[f];
    size_t i0 = (size_t)vi.x*64 + b, i1 = (size_t)vi.y*64 + b, i2 = (size_t)vi.z*64 + b;
    float p0x = d_Sx[i0], p0y = d_Sy[i0], p0z = d_Sz[i0];
    float p1x = d_Sx[i1], p1y = d_Sy[i1], p1z = d_Sz[i1];
    float p2x = d_Sx[i2], p2y = d_Sy[i2], p2z = d_Sz[i2];
    float ax = __fsub_rn(p0x, p1x), ay = __fsub_rn(p0y, p1y), az = __fsub_rn(p0z, p1z);
    float bx = __fsub_rn(p1x, p2x), by = __fsub_rn(p1y, p2y), bz = __fsub_rn(p1z, p2z);
    float nx = fmaf(ay, bz, -__fmul_rn(az, by));
    float ny = fmaf(az, bx, -__fmul_rn(ax, bz));
    float nz = fmaf(ax, by, -__fmul_rn(ay, bx));
    float nrm = sqrtf(nx*nx + ny*ny + nz*nz);
    float den = fmaxf(nrm, 1e-12f);
    d_fnx[o] = __fdiv_rn(nx, den);
    d_fny[o] = __fdiv_rn(ny, den);
    d_fnz[o] = __fdiv_rn(nz, den);
}

// ---------------- kernel 4: vertex normals + SH color -------------------------
__global__ __launch_bounds__(256) void color_k(const int* __restrict__ point_buf,
                                               float* __restrict__ out)
{
    __shared__ float sm[96][65];
    const int tid = threadIdx.x;
    const int b = tid & 63;
    const int v0 = blockIdx.x * 32;
    const float* M = d_rotM + b*9;
    float m0=M[0],m1=M[1],m2=M[2],m3=M[3],m4=M[4],m5=M[5],m6=M[6],m7=M[7],m8=M[8];
    const float* g = d_gg + b*27;

    #pragma unroll
    for (int it = 0; it < 8; it++) {
        int vl = (tid >> 6) + it*4;
        int v = v0 + vl;
        if (v < NV) {
            float sx = 0.f, sy = 0.f, sz = 0.f;
            #pragma unroll
            for (int k = 0; k < 8; k++) {
                int f = point_buf[v*8 + k];        // uniform broadcast
                size_t idx = (size_t)f*64 + b;     // coalesced
                sx = __fadd_rn(sx, d_fnx[idx]);
                sy = __fadd_rn(sy, d_fny[idx]);
                sz = __fadd_rn(sz, d_fnz[idx]);
            }
            float nrm = sqrtf(sx*sx + sy*sy + sz*sz);
            float den = fmaxf(nrm, 1e-12f);
            sx = __fdiv_rn(sx, den);
            sy = __fdiv_rn(sy, den);
            sz = __fdiv_rn(sz, den);
            float nx = fmaf(m0,sx, fmaf(m1,sy, m2*sz));
            float ny = fmaf(m3,sx, fmaf(m4,sy, m5*sz));
            float nz = fmaf(m6,sx, fmaf(m7,sy, m8*sz));

            float Y[9];
            Y[0] = 0.886226925452758f;
            Y[1] = -1.772453850905516f * ny;
            Y[2] =  1.772453850905516f * nz;
            Y[3] = -1.772453850905516f * nx;
            Y[4] =  2.427050983124842f * nx * ny;
            Y[5] = -2.427050983124842f * ny * nz;
            Y[6] =  0.700629269224046f * (3.0f*nz*nz - 1.0f);
            Y[7] = -2.427050983124842f * nx * nz;
            Y[8] =  1.213525491562421f * (nx*nx - ny*ny);

            float cr = 0.f, cg = 0.f, cb = 0.f;
            #pragma unroll
            for (int k = 0; k < 9; k++) {
                cr = fmaf(Y[k], g[k*3+0], cr);
                cg = fmaf(Y[k], g[k*3+1], cg);
                cb = fmaf(Y[k], g[k*3+2], cb);
            }
            size_t ti = (size_t)v*64 + b;
            sm[vl*3+0][b] = cr * d_txR[ti];
            sm[vl*3+1][b] = cg * d_txG[ti];
            sm[vl*3+2][b] = cb * d_txB[ti];
        }
    }
    __syncthreads();
    int nv = NV - v0; if (nv > 32) nv = 32;
    size_t obase = (size_t)NB*NV*3;
    if (nv == 32) {
        #pragma unroll
        for (int j = 0; j < 24; j++) {
            int idx = tid + j*256;
            int bb = (unsigned)idx / 96u, e = idx - bb*96;
            out[obase + ((size_t)bb*NV + v0)*3 + e] = sm[e][bb];
        }
    } else {
        int ne = 3*nv;
        for (int idx = tid; idx < 64*ne; idx += 256) {
            int bb = idx / ne, e = idx - bb*ne;
            out[obase + ((size_t)bb*NV + v0)*3 + e] = sm[e][bb];
        }
    }
}

// ---------------- kernel 5: landmarks -----------------------------------------
__global__ void lm_k(const int* __restrict__ keypoints,
                     const float* __restrict__ P,
                     const float* __restrict__ fv,
                     float* __restrict__ out)
{
    int j = threadIdx.x;
    int b = blockIdx.x;
    if (j >= 68) return;
    int v = keypoints[j];
    const float* p = fv + ((size_t)b*NV + v)*3;
    float x = p[0], y = p[1], z = p[2];
    float px = x*P[0] + y*P[3] + z*P[6];
    float py = x*P[1] + y*P[4] + z*P[7];
    float pz = x*P[2] + y*P[5] + z*P[8];
    float* o = out + (size_t)2*NB*NV*3 + ((size_t)b*68 + j)*2;
    o[0] = __fdiv_rn(px, pz);
    o[1] = __fdiv_rn(py, pz);
}

// ---------------- launch -------------------------------------------------------
extern "C" void kernel_launch(void* const* d_in, const int* in_sizes, int n_in,
                              void* d_out, int out_size)
{
    const float* coeffs    = (const float*)d_in[0];
    const float* meanshape = (const float*)d_in[1];
    const float* idBase    = (const float*)d_in[2];
    const float* exBase    = (const float*)d_in[3];
    const float* meantex   = (const float*)d_in[4];
    const float* texBase   = (const float*)d_in[5];
    const float* persc     = (const float*)d_in[6];
    const float* init_lit  = (const float*)d_in[7];
    const int*   point_buf = (const int*)d_in[8];
    const int*   face_buf  = (const int*)d_in[9];
    const int*   keypoints = (const int*)d_in[10];
    float* out = (float*)d_out;

    setup_k<<<(NF + 255)/256, 256>>>(coeffs, init_lit, face_buf);
    gemm_k<<<(TN + 127)/128, 256>>>(idBase, exBase, texBase, meanshape, meantex);

    transform_k<<<(NV + 31)/32, 256>>>(coeffs, out);
    fnorm_k<<<(NF + 1 + 3)/4, 256>>>();
    color_k<<<(NV + 31)/32, 256>>>(point_buf, out);

    lm_k<<<NB, 128>>>(keypoints, persc, out, out);
}